// round 1
// baseline (speedup 1.0000x reference)
#include <cuda_runtime.h>
#include <math.h>

#define Bx   8
#define Nx   256
#define Dx   128
#define OUTx 128
#define BN   (Bx*Nx)      // 2048

// ---------------- scratch (device globals; no allocations allowed) -------
__device__ float g_A [BN*OUTx];   // h @ Wm1[0:128]
__device__ float g_Bm[BN*OUTx];   // h @ Wm1[128:256]
__device__ float g_as[BN];        // h . Wa[0:128]
__device__ float g_bs[BN];        // h . Wa[128:256]
__device__ float g_S [BN*OUTx];   // sum_j w_ij * relu(pre_ij)
__device__ float g_c [BN];        // sum_j w_ij
__device__ float g_M [OUTx*OUTx]; // Wm2 @ Wu_bot
__device__ float g_vb[OUTx];      // bm2 @ Wu_bot + bu

// ---------------- kernel 1: per-node precompute ---------------------------
// grid 128, block 256.  16 nodes per block; half 0 -> A, half 1 -> B.
__global__ void k_pre(const float* __restrict__ h,
                      const float* __restrict__ Wm1,
                      const float* __restrict__ Wa)
{
    __shared__ float hs[16*128];
    const int row0 = blockIdx.x * 16;
    const int t = threadIdx.x;
    const int c = t & 127, half = t >> 7;

    for (int k = t; k < 2048; k += 256) hs[k] = h[row0*128 + k];
    __syncthreads();

    float acc[16];
#pragma unroll
    for (int r = 0; r < 16; r++) acc[r] = 0.f;

    const float* W = Wm1 + half*128*128 + c;
#pragma unroll 4
    for (int d = 0; d < 128; d++) {
        float w = W[d*128];
#pragma unroll
        for (int r = 0; r < 16; r++)
            acc[r] = fmaf(hs[r*128 + d], w, acc[r]);
    }
    float* dst = half ? g_Bm : g_A;
#pragma unroll
    for (int r = 0; r < 16; r++)
        dst[(row0 + r)*128 + c] = acc[r];

    // scalar dots: warp w handles rows w and w+8
    const int wp = t >> 5, l = t & 31;
    for (int r = wp; r < 16; r += 8) {
        float sa = 0.f, sb = 0.f;
        for (int k = l; k < 128; k += 32) {
            float hv = hs[r*128 + k];
            sa = fmaf(hv, Wa[k],       sa);
            sb = fmaf(hv, Wa[128 + k], sb);
        }
#pragma unroll
        for (int o = 16; o; o >>= 1) {
            sa += __shfl_xor_sync(0xffffffffu, sa, o);
            sb += __shfl_xor_sync(0xffffffffu, sb, o);
        }
        if (l == 0) { g_as[row0 + r] = sa; g_bs[row0 + r] = sb; }
    }
}

// ---------------- kernel 2: folded weight matrices -------------------------
// grid 129, block 128. blocks 0..127: M rows; block 128: vb.
__global__ void k_mat(const float* __restrict__ Wm2,
                      const float* __restrict__ bm2,
                      const float* __restrict__ Wu,
                      const float* __restrict__ bu)
{
    const int d = blockIdx.x;
    const int c = threadIdx.x;
    if (d < 128) {
        float acc = 0.f;
#pragma unroll 4
        for (int k = 0; k < 128; k++)
            acc = fmaf(Wm2[d*128 + k], Wu[(128 + k)*128 + c], acc);
        g_M[d*128 + c] = acc;
    } else {
        float acc = bu[c];
#pragma unroll 4
        for (int k = 0; k < 128; k++)
            acc = fmaf(bm2[k], Wu[(128 + k)*128 + c], acc);
        g_vb[c] = acc;
    }
}

// ---------------- kernel 3: pair softmax + weighted aggregation -----------
// grid (16,8): x = i-tile of 16, y = batch.  block 256 threads.
// dynamic smem: B tile of the whole batch (256x128) + small arrays.
#define K2_BF   (256*128)
#define K2_SMEM ((K2_BF + 256 + 128 + 128 + 256 + 256 + 32 + 256) * sizeof(float))

__global__ void k_pair(const float* __restrict__ dist,
                       const int*   __restrict__ adj,
                       const float* __restrict__ Wm1,
                       const float* __restrict__ bm1,
                       const float* __restrict__ Wa,
                       const float* __restrict__ ba)
{
    extern __shared__ float sm[];
    float* Bsh   = sm;               // 32768
    float* bssh  = Bsh   + K2_BF;    // 256
    float* wdsh  = bssh  + 256;      // 128
    float* bm1sh = wdsh  + 128;      // 128
    float* dsh   = bm1sh + 128;      // 256
    float* wsh   = dsh   + 256;      // 256
    float* red   = wsh   + 256;      // 32
    float* part  = red   + 32;       // 256

    const int t    = threadIdx.x;          // 0..255
    const int b    = blockIdx.y;
    const int i0   = blockIdx.x * 16;
    const int lane = t & 31, wrp = t >> 5;

    // batch-wide B tile into shared (128 KB)
    {
        const float4* src = (const float4*)(g_Bm + b*Nx*128);
        float4*       dstv = (float4*)Bsh;
        for (int k = t; k < K2_BF/4; k += 256) dstv[k] = src[k];
    }
    bssh[t] = g_bs[b*Nx + t];
    if (t < 128) { wdsh[t] = Wm1[256*128 + t]; bm1sh[t] = bm1[t]; }
    const float wa_d = Wa[256];
    const float bav  = ba[0];
    __syncthreads();

    const int c = t & 127, half = t >> 7;

    for (int ii = 0; ii < 16; ii++) {
        const int i  = i0 + ii;
        const int ig = b*Nx + i;

        // ---- phase 1: logits + softmax weights over j (t == j) ----
        const float a_i = g_as[ig];
        const float dij = dist[(long)ig*Nx + t];
        const int   m   = adj [(long)ig*Nx + t];
        float x = fmaf(dij, wa_d, a_i + bssh[t] + bav);
        x = (x >= 0.f) ? x : 0.2f * x;               // leaky_relu(0.2)
        const float logit = m ? x : -1e9f;

        float v = logit;
#pragma unroll
        for (int o = 16; o; o >>= 1) v = fmaxf(v, __shfl_xor_sync(0xffffffffu, v, o));
        if (lane == 0) red[wrp] = v;
        __syncthreads();
        float mx = red[0];
#pragma unroll
        for (int k = 1; k < 8; k++) mx = fmaxf(mx, red[k]);

        const float e  = expf(logit - mx);
        const float wsv = m ? e : 0.f;
        float s1 = e, s2 = wsv;
#pragma unroll
        for (int o = 16; o; o >>= 1) {
            s1 += __shfl_xor_sync(0xffffffffu, s1, o);
            s2 += __shfl_xor_sync(0xffffffffu, s2, o);
        }
        if (lane == 0) { red[8 + wrp] = s1; red[16 + wrp] = s2; }
        __syncthreads();
        float sum = 0.f, cs = 0.f;
#pragma unroll
        for (int k = 0; k < 8; k++) { sum += red[8 + k]; cs += red[16 + k]; }
        const float inv = 1.0f / sum;
        wsh[t] = wsv * inv;
        dsh[t] = dij;
        if (t == 0) g_c[ig] = cs * inv;
        __syncthreads();

        // ---- phase 2: S[c] = sum_j w_j * relu(A_i[c] + B_j[c] + d_j*wd[c] + bm1[c])
        const float Ac  = g_A[(long)ig*128 + c] + bm1sh[c];
        const float wdc = wdsh[c];
        const float* Bp = Bsh + half*128*128 + c;
        const float* dp = dsh + half*128;
        const float* wq = wsh + half*128;
        float acc0 = 0.f, acc1 = 0.f;
#pragma unroll 8
        for (int jj = 0; jj < 128; jj += 2) {
            float p0 = fmaf(dp[jj],   wdc, Ac) + Bp[jj*128];
            acc0 = fmaf(wq[jj],   fmaxf(p0, 0.f), acc0);
            float p1 = fmaf(dp[jj+1], wdc, Ac) + Bp[(jj+1)*128];
            acc1 = fmaf(wq[jj+1], fmaxf(p1, 0.f), acc1);
        }
        part[t] = acc0 + acc1;
        __syncthreads();
        if (half == 0)
            g_S[(long)ig*128 + c] = part[c] + part[128 + c];
        __syncthreads();   // protect dsh/wsh/red before next i
    }
}

// ---------------- kernel 4: fused epilogue ---------------------------------
// out = relu( h@Wu_top + S@M + c*vb )       (vb already contains bm2@Wu_bot+bu)
// grid 128, block 256.
__global__ void k_out(const float* __restrict__ h,
                      const float* __restrict__ Wu,
                      float* __restrict__ out)
{
    __shared__ float hs[2048], Ss[2048];
    __shared__ float part[4096];
    const int row0 = blockIdx.x * 16;
    const int t = threadIdx.x;
    const int c = t & 127, half = t >> 7;

    for (int k = t; k < 2048; k += 256) {
        hs[k] = h  [row0*128 + k];
        Ss[k] = g_S[row0*128 + k];
    }
    __syncthreads();

    float acc[16];
#pragma unroll
    for (int r = 0; r < 16; r++) acc[r] = 0.f;

    if (half == 0) {
#pragma unroll 4
        for (int d = 0; d < 128; d++) {
            float w = Wu[d*128 + c];
#pragma unroll
            for (int r = 0; r < 16; r++) acc[r] = fmaf(hs[r*128 + d], w, acc[r]);
        }
    } else {
#pragma unroll 4
        for (int d = 0; d < 128; d++) {
            float w = g_M[d*128 + c];
#pragma unroll
            for (int r = 0; r < 16; r++) acc[r] = fmaf(Ss[r*128 + d], w, acc[r]);
        }
    }
#pragma unroll
    for (int r = 0; r < 16; r++) part[half*2048 + r*128 + c] = acc[r];
    __syncthreads();

    if (half == 0) {
        const float vbc = g_vb[c];
#pragma unroll
        for (int r = 0; r < 16; r++) {
            float v = part[r*128 + c] + part[2048 + r*128 + c]
                    + g_c[row0 + r] * vbc;
            out[(row0 + r)*128 + c] = fmaxf(v, 0.f);
        }
    }
}

// ---------------- launch ----------------------------------------------------
extern "C" void kernel_launch(void* const* d_in, const int* in_sizes, int n_in,
                              void* d_out, int out_size)
{
    const float* h    = (const float*)d_in[0];
    const int*   adj  = (const int*)  d_in[1];
    const float* dist = (const float*)d_in[2];
    const float* Wm1  = (const float*)d_in[3];
    const float* bm1  = (const float*)d_in[4];
    const float* Wm2  = (const float*)d_in[5];
    const float* bm2  = (const float*)d_in[6];
    const float* Wa   = (const float*)d_in[7];
    const float* ba   = (const float*)d_in[8];
    const float* Wu   = (const float*)d_in[9];
    const float* bu   = (const float*)d_in[10];
    float* out = (float*)d_out;

    cudaFuncSetAttribute(k_pair, cudaFuncAttributeMaxDynamicSharedMemorySize,
                         (int)K2_SMEM);

    k_pre <<<128, 256>>>(h, Wm1, Wa);
    k_mat <<<129, 128>>>(Wm2, bm2, Wu, bu);
    k_pair<<<dim3(16, 8), 256, K2_SMEM>>>(dist, adj, Wm1, bm1, Wa, ba);
    k_out <<<128, 256>>>(h, Wu, out);
}

// round 2
// speedup vs baseline: 1.9863x; 1.9863x over previous
#include <cuda_runtime.h>
#include <math.h>

#define Nx   256
#define BN   2048      // 8*256

// ---------------- scratch ----------------
__device__ float g_A [BN*128];   // h @ Wm1[0:128]
__device__ float g_Bm[BN*128];   // h @ Wm1[128:256]
__device__ float g_as[BN];
__device__ float g_bs[BN];
__device__ float g_S [BN*128];   // sum_j w_ij * relu(pre_ij)
__device__ float g_c [BN];       // sum_j w_ij
__device__ float g_M [128*128];  // Wm2 @ Wu_bot
__device__ float g_vb[128];      // bm2 @ Wu_bot + bu

// =======================================================================
// Stage 1: GEMMs (h@Wm1 -> g_A/g_Bm, Wm2@Wu_bot -> g_M), dots, g_vb
// grid 141, block 256
// =======================================================================
__global__ void __launch_bounds__(256) k_stage1(
    const float* __restrict__ h,   const float* __restrict__ Wm1,
    const float* __restrict__ Wa,  const float* __restrict__ Wm2,
    const float* __restrict__ bm2, const float* __restrict__ Wu,
    const float* __restrict__ bu)
{
    const int bid = blockIdx.x;
    const int t   = threadIdx.x;

    if (bid < 132) {
        // ---- register-tiled GEMM: C[64x64] tile, K=128, BK=32, 4x4 micro
        __shared__ float As[32][68];
        __shared__ float Ws[32][68];
        const float *A, *W;
        float* dst;
        int row0, col0;
        if (bid < 128) {
            int mt = bid >> 2, nt = bid & 3;
            row0 = mt * 64;
            A = h;
            W = Wm1 + (nt >= 2 ? 128*128 : 0);
            col0 = (nt & 1) * 64;
            dst = (nt >= 2) ? g_Bm : g_A;
        } else {
            int bb = bid - 128;
            row0 = (bb >> 1) * 64;
            A = Wm2;
            W = Wu + 128*128;
            col0 = (bb & 1) * 64;
            dst = g_M;
        }
        const int ty = t >> 4, tx = t & 15;
        float acc[4][4];
#pragma unroll
        for (int r = 0; r < 4; r++)
#pragma unroll
            for (int c = 0; c < 4; c++) acc[r][c] = 0.f;

        for (int k0 = 0; k0 < 128; k0 += 32) {
#pragma unroll
            for (int n = 0; n < 2; n++) {           // A tile 64x32 transposed
                int l  = t + n*256;
                int r  = l >> 3;
                int kq = (l & 7) * 4;
                float4 v = *(const float4*)&A[(row0 + r)*128 + k0 + kq];
                As[kq+0][r] = v.x; As[kq+1][r] = v.y;
                As[kq+2][r] = v.z; As[kq+3][r] = v.w;
            }
#pragma unroll
            for (int n = 0; n < 2; n++) {           // W tile 32x64
                int l  = t + n*256;
                int wk = l >> 4;
                int wn = (l & 15) * 4;
                *(float4*)&Ws[wk][wn] =
                    *(const float4*)&W[(k0 + wk)*128 + col0 + wn];
            }
            __syncthreads();
#pragma unroll
            for (int kk = 0; kk < 32; kk++) {
                float4 a4 = *(const float4*)&As[kk][ty*4];
                float4 b4 = *(const float4*)&Ws[kk][tx*4];
                acc[0][0] = fmaf(a4.x, b4.x, acc[0][0]);
                acc[0][1] = fmaf(a4.x, b4.y, acc[0][1]);
                acc[0][2] = fmaf(a4.x, b4.z, acc[0][2]);
                acc[0][3] = fmaf(a4.x, b4.w, acc[0][3]);
                acc[1][0] = fmaf(a4.y, b4.x, acc[1][0]);
                acc[1][1] = fmaf(a4.y, b4.y, acc[1][1]);
                acc[1][2] = fmaf(a4.y, b4.z, acc[1][2]);
                acc[1][3] = fmaf(a4.y, b4.w, acc[1][3]);
                acc[2][0] = fmaf(a4.z, b4.x, acc[2][0]);
                acc[2][1] = fmaf(a4.z, b4.y, acc[2][1]);
                acc[2][2] = fmaf(a4.z, b4.z, acc[2][2]);
                acc[2][3] = fmaf(a4.z, b4.w, acc[2][3]);
                acc[3][0] = fmaf(a4.w, b4.x, acc[3][0]);
                acc[3][1] = fmaf(a4.w, b4.y, acc[3][1]);
                acc[3][2] = fmaf(a4.w, b4.z, acc[3][2]);
                acc[3][3] = fmaf(a4.w, b4.w, acc[3][3]);
            }
            __syncthreads();
        }
#pragma unroll
        for (int r = 0; r < 4; r++)
            *(float4*)&dst[(row0 + ty*4 + r)*128 + col0 + tx*4] =
                make_float4(acc[r][0], acc[r][1], acc[r][2], acc[r][3]);

    } else if (bid < 140) {
        // ---- attention scalar dots: g_as, g_bs
        __shared__ __align__(16) float was[272];
        for (int k = t; k < 257; k += 256) was[k] = Wa[k];
        __syncthreads();
        const int wrp = t >> 5, lane = t & 31;
        const int rowbase = (bid - 132) * 256 + wrp * 32;
        float4 wa1 = *(const float4*)&was[lane*4];
        float4 wa2 = *(const float4*)&was[128 + lane*4];
        for (int rr = 0; rr < 32; rr++) {
            int row = rowbase + rr;
            float4 hv = *(const float4*)&h[row*128 + lane*4];
            float sa = hv.x*wa1.x + hv.y*wa1.y + hv.z*wa1.z + hv.w*wa1.w;
            float sb = hv.x*wa2.x + hv.y*wa2.y + hv.z*wa2.z + hv.w*wa2.w;
#pragma unroll
            for (int o = 16; o; o >>= 1) {
                sa += __shfl_xor_sync(0xffffffffu, sa, o);
                sb += __shfl_xor_sync(0xffffffffu, sb, o);
            }
            if (lane == 0) { g_as[row] = sa; g_bs[row] = sb; }
        }
    } else {
        // ---- g_vb = bm2 @ Wu_bot + bu
        if (t < 128) {
            float acc = bu[t];
#pragma unroll 8
            for (int k = 0; k < 128; k++)
                acc = fmaf(bm2[k], Wu[(128 + k)*128 + t], acc);
            g_vb[t] = acc;
        }
    }
}

// =======================================================================
// k_pair: softmax + weighted relu aggregation
// grid (16,8), block 512, dyn smem 205824B
// =======================================================================
#define PAIR_SMEM ((32768 + 16384 + 2048 + 256) * 4)

__global__ void __launch_bounds__(512, 1) k_pair(
    const float* __restrict__ dist, const int* __restrict__ adj,
    const float* __restrict__ Wm1,  const float* __restrict__ bm1,
    const float* __restrict__ Wa,   const float* __restrict__ ba)
{
    extern __shared__ float sm[];
    float*  Bsh  = sm;                       // 256*128 floats (128KB)
    float4* dwsh = (float4*)(sm + 32768);    // 16*256 float4 {d,d,w,w} (64KB)
    float*  Ash  = sm + 32768 + 16384;       // 16*128 (A + bm1)
    float*  bssh = Ash + 2048;               // 256

    const int t = threadIdx.x;
    const int b = blockIdx.y, i0 = blockIdx.x * 16;
    const int lane = t & 31, wrp = t >> 5;

    // ---- fills
    {
        const float4* src = (const float4*)(g_Bm + (long)b*Nx*128);
        float4* d4 = (float4*)Bsh;
#pragma unroll
        for (int k = 0; k < 16; k++) d4[t + k*512] = src[t + k*512];
    }
#pragma unroll
    for (int k = 0; k < 4; k++) {
        int idx = t + k*512;
        Ash[idx] = g_A[(long)(b*Nx + i0)*128 + idx] + bm1[idx & 127];
    }
    if (t < 256) bssh[t] = g_bs[b*Nx + t];
    __syncthreads();

    // ---- phase 1: warp wrp handles i = i0 + wrp
    const float wa_d = Wa[256];
    {
        const int ig = b*Nx + i0 + wrp;
        const float a_i = g_as[ig] + ba[0];
        float l[8], dv[8]; int mk[8];
#pragma unroll
        for (int jj = 0; jj < 8; jj++) {
            int j = jj*32 + lane;
            float d = dist[(long)ig*Nx + j];
            int   m = adj [(long)ig*Nx + j];
            float x = fmaf(d, wa_d, a_i + bssh[j]);
            x = (x >= 0.f) ? x : 0.2f * x;
            l[jj] = m ? x : -1e9f;
            dv[jj] = d; mk[jj] = m;
        }
        float mx = l[0];
#pragma unroll
        for (int jj = 1; jj < 8; jj++) mx = fmaxf(mx, l[jj]);
#pragma unroll
        for (int o = 16; o; o >>= 1) mx = fmaxf(mx, __shfl_xor_sync(0xffffffffu, mx, o));
        float sum = 0.f, cs = 0.f;
#pragma unroll
        for (int jj = 0; jj < 8; jj++) {
            float e = expf(l[jj] - mx);
            l[jj] = e;
            sum += e;
            cs  += mk[jj] ? e : 0.f;
        }
#pragma unroll
        for (int o = 16; o; o >>= 1) {
            sum += __shfl_xor_sync(0xffffffffu, sum, o);
            cs  += __shfl_xor_sync(0xffffffffu, cs,  o);
        }
        float inv = 1.f / sum;
#pragma unroll
        for (int jj = 0; jj < 8; jj++) {
            int j = jj*32 + lane;
            float w = mk[jj] ? l[jj]*inv : 0.f;
            dwsh[wrp*256 + j] = make_float4(dv[jj], dv[jj], w, w);
        }
        if (lane == 0) g_c[ig] = cs * inv;
    }

    // ---- per-thread registers for phase 2
    const int cp = t & 63, q = t >> 6;
    unsigned long long a2[16], acc2[16];
#pragma unroll
    for (int i = 0; i < 16; i++) {
        a2[i]   = *(const unsigned long long*)&Ash[i*128 + cp*2];
        acc2[i] = 0ull;
    }
    const unsigned long long wd2 =
        *(const unsigned long long*)&Wm1[256*128 + cp*2];
    __syncthreads();

    // ---- phase 2: acc_i[c2] += w_ij * relu(A_ic + B_jc + d_ij*wd_c)
    const ulonglong2* dw2 = (const ulonglong2*)dwsh;
#pragma unroll 1
    for (int jj = 0; jj < 32; jj++) {
        int j = jj*8 + q;
        unsigned long long b2 = *(const unsigned long long*)&Bsh[j*128 + cp*2];
        const ulonglong2* p = dw2 + j;
#pragma unroll
        for (int i = 0; i < 16; i++) {
            ulonglong2 dw = p[i*256];
            asm("{\n\t"
                ".reg .b64 tt;\n\t"
                ".reg .f32 lo, hi;\n\t"
                "add.rn.f32x2 tt, %1, %2;\n\t"
                "fma.rn.f32x2 tt, %3, %4, tt;\n\t"
                "mov.b64 {lo, hi}, tt;\n\t"
                "max.f32 lo, lo, 0f00000000;\n\t"
                "max.f32 hi, hi, 0f00000000;\n\t"
                "mov.b64 tt, {lo, hi};\n\t"
                "fma.rn.f32x2 %0, %5, tt, %0;\n\t"
                "}"
                : "+l"(acc2[i])
                : "l"(a2[i]), "l"(b2), "l"(dw.x), "l"(wd2), "l"(dw.y));
        }
    }
    __syncthreads();

    // ---- reduce over q (8 partials), reuse dwsh region
    unsigned long long* part = (unsigned long long*)dwsh;
#pragma unroll
    for (int i = 0; i < 16; i++) part[(i*8 + q)*64 + cp] = acc2[i];
    __syncthreads();
#pragma unroll
    for (int rep = 0; rep < 2; rep++) {
        int it = t + rep*512;
        int i = it >> 6, cpp = it & 63;
        float2 s = make_float2(0.f, 0.f);
#pragma unroll
        for (int qq = 0; qq < 8; qq++) {
            float2 v = *(float2*)&part[(i*8 + qq)*64 + cpp];
            s.x += v.x; s.y += v.y;
        }
        *(float2*)&g_S[(long)(b*Nx + i0 + i)*128 + cpp*2] = s;
    }
}

// =======================================================================
// k_out: out = relu( h@Wu_top + S@M + g_c*vb )
// grid (64,2), block 256, BM=32 BN=64 BK=32, 2x4 micro
// =======================================================================
__global__ void __launch_bounds__(256) k_out(
    const float* __restrict__ h, const float* __restrict__ Wu,
    float* __restrict__ out)
{
    __shared__ float As[32][36];
    __shared__ float Ws[32][68];
    const int t = threadIdx.x;
    const int row0 = blockIdx.x * 32, col0 = blockIdx.y * 64;
    const int ty = t >> 4, tx = t & 15;
    float acc[2][4];
#pragma unroll
    for (int r = 0; r < 2; r++)
#pragma unroll
        for (int c = 0; c < 4; c++) acc[r][c] = 0.f;

    for (int k0 = 0; k0 < 256; k0 += 32) {
        {   // A tile 32x32 (concat [h | S]) transposed
            int r  = t >> 3;
            int kq = (t & 7) * 4;
            int kg = k0 + kq;
            const float* src = (kg < 128) ? &h  [(row0 + r)*128 + kg]
                                          : &g_S[(row0 + r)*128 + kg - 128];
            float4 v = *(const float4*)src;
            As[kq+0][r] = v.x; As[kq+1][r] = v.y;
            As[kq+2][r] = v.z; As[kq+3][r] = v.w;
        }
#pragma unroll
        for (int n = 0; n < 2; n++) {   // W tile 32x64 (concat [Wu_top ; M])
            int l  = t + n*256;
            int wk = l >> 4;
            int wn = (l & 15) * 4;
            int kg = k0 + wk;
            const float* src = (kg < 128) ? &Wu [kg*128 + col0 + wn]
                                          : &g_M[(kg - 128)*128 + col0 + wn];
            *(float4*)&Ws[wk][wn] = *(const float4*)src;
        }
        __syncthreads();
#pragma unroll
        for (int kk = 0; kk < 32; kk++) {
            float2 a2 = *(const float2*)&As[kk][ty*2];
            float4 b4 = *(const float4*)&Ws[kk][tx*4];
            acc[0][0] = fmaf(a2.x, b4.x, acc[0][0]);
            acc[0][1] = fmaf(a2.x, b4.y, acc[0][1]);
            acc[0][2] = fmaf(a2.x, b4.z, acc[0][2]);
            acc[0][3] = fmaf(a2.x, b4.w, acc[0][3]);
            acc[1][0] = fmaf(a2.y, b4.x, acc[1][0]);
            acc[1][1] = fmaf(a2.y, b4.y, acc[1][1]);
            acc[1][2] = fmaf(a2.y, b4.z, acc[1][2]);
            acc[1][3] = fmaf(a2.y, b4.w, acc[1][3]);
        }
        __syncthreads();
    }

    float4 vb4 = *(const float4*)&g_vb[col0 + tx*4];
#pragma unroll
    for (int r = 0; r < 2; r++) {
        int row = row0 + ty*2 + r;
        float cr = g_c[row];
        float4 v;
        v.x = fmaxf(fmaf(cr, vb4.x, acc[r][0]), 0.f);
        v.y = fmaxf(fmaf(cr, vb4.y, acc[r][1]), 0.f);
        v.z = fmaxf(fmaf(cr, vb4.z, acc[r][2]), 0.f);
        v.w = fmaxf(fmaf(cr, vb4.w, acc[r][3]), 0.f);
        *(float4*)&out[row*128 + col0 + tx*4] = v;
    }
}

// =======================================================================
extern "C" void kernel_launch(void* const* d_in, const int* in_sizes, int n_in,
                              void* d_out, int out_size)
{
    const float* h    = (const float*)d_in[0];
    const int*   adj  = (const int*)  d_in[1];
    const float* dist = (const float*)d_in[2];
    const float* Wm1  = (const float*)d_in[3];
    const float* bm1  = (const float*)d_in[4];
    const float* Wm2  = (const float*)d_in[5];
    const float* bm2  = (const float*)d_in[6];
    const float* Wa   = (const float*)d_in[7];
    const float* ba   = (const float*)d_in[8];
    const float* Wu   = (const float*)d_in[9];
    const float* bu   = (const float*)d_in[10];
    float* out = (float*)d_out;

    cudaFuncSetAttribute(k_pair, cudaFuncAttributeMaxDynamicSharedMemorySize,
                         PAIR_SMEM);

    k_stage1<<<141, 256>>>(h, Wm1, Wa, Wm2, bm2, Wu, bu);
    k_pair  <<<dim3(16, 8), 512, PAIR_SMEM>>>(dist, adj, Wm1, bm1, Wa, ba);
    k_out   <<<dim3(64, 2), 256>>>(h, Wu, out);
}